// round 8
// baseline (speedup 1.0000x reference)
#include <cuda_runtime.h>
#include <math.h>

// ---------------- static config ----------------
static constexpr int NB = 8;
static constexpr int ND = 256;
static constexpr int NC = 64;
static constexpr int NHID = 128;
static constexpr int NS = 64;
static constexpr int NHH = 28, NWW = 28;
static constexpr int NL = NHH * NWW;        // 784
static constexpr int NHEAD = 16;
static constexpr int NPAIRS = NB * NL / 2;  // 3136
static constexpr int PPB = NL / 2;          // 392
static constexpr int GRID = 296;            // 2 blocks/SM on 148 SMs

// ---------------- scratch arena ----------------
static constexpr long O_X1O   = 0;                          // (8,64,784)
static constexpr long O_T2    = O_X1O   + (long)NB*NC*NL;   // (8,128,784)
static constexpr long O_TMP1  = O_T2    + (long)NB*NHID*NL; // (8,64,784)
static constexpr long O_BCDT0 = O_TMP1  + (long)NB*NC*NL;   // (8,192,784)
static constexpr long O_CM    = O_BCDT0 + (long)NB*192*NL;  // (8,64,784) conv3x3(Cm)
static constexpr long O_H     = O_CM    + (long)NB*NC*NL;   // (8,64,64)
static constexpr long O_U     = O_H     + (long)NB*NC*NS;   // (8,64,64)
static constexpr long O_QKV   = O_U     + (long)NB*NC*NS;   // (8,192,784)
static constexpr long O_O     = O_QKV   + (long)NB*192*NL;  // (8,64,784)
static constexpr long O_XA    = O_O     + (long)NB*NC*NL;   // (8,256,784)
static constexpr long O_M1    = O_XA    + (long)NB*ND*NL;   // (8,128,784)
static constexpr long SCR_TOTAL = O_M1 + (long)NB*NHID*NL;

__device__ __align__(16) float g_scr[SCR_TOTAL];

// ---------------- grid barrier (generation counter, replay-safe) ----------------
__device__ unsigned g_bar_count = 0;
__device__ volatile unsigned g_bar_gen = 0;

__device__ __forceinline__ void grid_barrier() {
    __syncthreads();
    if (threadIdx.x == 0) {
        unsigned gen = g_bar_gen;
        __threadfence();
        if (atomicAdd(&g_bar_count, 1) == GRID - 1) {
            g_bar_count = 0;
            __threadfence();
            g_bar_gen = gen + 1;
        } else {
            while (g_bar_gen == gen) { __nanosleep(64); }
        }
        __threadfence();
    }
    __syncthreads();
}

enum { M_NONE = 0, M_ADD_BN, M_BN_RELU, M_BN_ADD, M_BN };

struct MegaParams {
    const float *x, *dw1_w, *dw1_b, *bn_dw1, *f1_w, *f1_b, *f2_w, *f2_b,
                *g_w, *g_b, *bn_g, *dw2_w, *dw2_b,
                *h1w, *v1w, *h2w, *v2w, *bn_mra,
                *bcdt_w, *ssd_dw, *hz_w, *ow, *A, *D,
                *qkv_w, *proj_w, *bn_n4, *mlp1_w, *bn_mlp, *mlp2_w, *bn_n1;
    float* out;
};

// ---------------- unit: pointwise conv (16 outputs x 256 pixel-pairs) ----------------
template <int CIN>
__device__ void pw_unit(float* sm, int otile, int pslot,
                        const float* __restrict__ in, long ibs,
                        const float* __restrict__ w, int cout,
                        const float* __restrict__ bias, const float* __restrict__ bnp,
                        const float* __restrict__ res, long rbs,
                        float* __restrict__ out, long obs, int mode) {
    __syncthreads();
    float* ws = sm;  // transposed: ws[c*16+i]
    int obase = otile * 16;
    for (int idx = threadIdx.x; idx < CIN * 16; idx += 256) {
        int c = idx >> 4, i = idx & 15;
        ws[idx] = w[(long)(obase + i) * CIN + c];
    }
    __syncthreads();
    int pp = pslot * 256 + threadIdx.x;
    if (pp >= NPAIRS) return;
    int b = pp / PPB;
    int l = (pp % PPB) * 2;
    const float2* ip2 = reinterpret_cast<const float2*>(in + (long)b * ibs + l);
    float a0[16], a1[16];
#pragma unroll
    for (int i = 0; i < 16; i++) { a0[i] = 0.f; a1[i] = 0.f; }
#pragma unroll 4
    for (int c = 0; c < CIN; c++) {
        float2 xv = ip2[c * (NL / 2)];
        const float* wc = ws + c * 16;
#pragma unroll
        for (int i = 0; i < 16; i++) {
            float wv = wc[i];
            a0[i] += wv * xv.x;
            a1[i] += wv * xv.y;
        }
    }
#pragma unroll
    for (int i = 0; i < 16; i++) {
        int o = obase + i;
        float s0 = a0[i], s1 = a1[i];
        if (bias) { s0 += bias[o]; s1 += bias[o]; }
        if (mode >= M_ADD_BN) {
            long roff = (long)b * rbs + (long)o * NL + l;
            if (mode == M_ADD_BN) {
                float2 rv = *reinterpret_cast<const float2*>(res + roff);
                s0 += rv.x; s1 += rv.y;
            }
            float g = bnp[o], be = bnp[cout + o], mm = bnp[2 * cout + o],
                  vv = bnp[3 * cout + o];
            float sc = g * rsqrtf(vv + 1e-5f);
            s0 = (s0 - mm) * sc + be;
            s1 = (s1 - mm) * sc + be;
            if (mode == M_BN_RELU) { s0 = fmaxf(s0, 0.f); s1 = fmaxf(s1, 0.f); }
            if (mode == M_BN_ADD) {
                float2 rv = *reinterpret_cast<const float2*>(res + roff);
                s0 += rv.x; s1 += rv.y;
            }
        }
        *reinterpret_cast<float2*>(out + (long)b * obs + (long)o * NL + l) =
            make_float2(s0, s1);
    }
}

// ---------------- unit: star MLP (relu6(f1)*f2) ----------------
__device__ void star_unit(float* sm, int otile, int pslot,
                          const float* __restrict__ in,
                          const float* __restrict__ w1, const float* __restrict__ b1,
                          const float* __restrict__ w2, const float* __restrict__ b2,
                          float* __restrict__ out) {
    __syncthreads();
    float* ws1 = sm;
    float* ws2 = sm + NC * 16;
    int obase = otile * 16;
    for (int idx = threadIdx.x; idx < NC * 16; idx += 256) {
        int c = idx >> 4, i = idx & 15;
        ws1[idx] = w1[(long)(obase + i) * NC + c];
        ws2[idx] = w2[(long)(obase + i) * NC + c];
    }
    __syncthreads();
    int pp = pslot * 256 + threadIdx.x;
    if (pp >= NPAIRS) return;
    int b = pp / PPB;
    int l = (pp % PPB) * 2;
    const float2* ip2 = reinterpret_cast<const float2*>(in + (long)b * NC * NL + l);
    float p0[16], p1[16], q0[16], q1[16];
#pragma unroll
    for (int i = 0; i < 16; i++) { p0[i] = p1[i] = q0[i] = q1[i] = 0.f; }
#pragma unroll 4
    for (int c = 0; c < NC; c++) {
        float2 xv = ip2[c * (NL / 2)];
        const float* w1c = ws1 + c * 16;
        const float* w2c = ws2 + c * 16;
#pragma unroll
        for (int i = 0; i < 16; i++) {
            p0[i] += w1c[i] * xv.x; p1[i] += w1c[i] * xv.y;
            q0[i] += w2c[i] * xv.x; q1[i] += w2c[i] * xv.y;
        }
    }
#pragma unroll
    for (int i = 0; i < 16; i++) {
        int o = obase + i;
        float h0 = fminf(fmaxf(p0[i] + b1[o], 0.f), 6.f);
        float h1 = fminf(fmaxf(p1[i] + b1[o], 0.f), 6.f);
        *reinterpret_cast<float2*>(out + ((long)b * NHID + o) * NL + l) =
            make_float2(h0 * (q0[i] + b2[o]), h1 * (q1[i] + b2[o]));
    }
}

// ---------------- unit: depthwise 7x7 ----------------
__device__ void dw7_unit(float* sm, int u, const float* __restrict__ in, long ibs,
                         const float* __restrict__ w, const float* __restrict__ bias,
                         const float* __restrict__ bnp,
                         float* __restrict__ out, long obs) {
    __syncthreads();
    float* pl = sm;          // 34x34
    float* wsh = sm + 1156;  // 49
    int c = u & 63, b = u >> 6;
    const float* ip = in + (long)b * ibs + (long)c * NL;
    int t = threadIdx.x;
    for (int i = t; i < 1156; i += 256) pl[i] = 0.f;
    if (t < 49) wsh[t] = w[c * 49 + t];
    __syncthreads();
    for (int i = t; i < NL; i += 256) {
        int y = i / NWW, x = i % NWW;
        pl[(y + 3) * 34 + x + 3] = ip[i];
    }
    __syncthreads();
    float sc = 1.f, sh = 0.f;
    if (bnp) {
        float g = bnp[c], be = bnp[NC + c], mm = bnp[2 * NC + c], vv = bnp[3 * NC + c];
        sc = g * rsqrtf(vv + 1e-5f);
        sh = be - mm * sc;
    }
    float bi = bias[c];
    for (int i = t; i < NL; i += 256) {
        int y = i / NWW, x = i % NWW;
        float s = 0.f;
#pragma unroll
        for (int ky = 0; ky < 7; ky++)
#pragma unroll
            for (int kx = 0; kx < 7; kx++)
                s += wsh[ky * 7 + kx] * pl[(y + ky) * 34 + x + kx];
        out[(long)b * obs + (long)c * NL + i] = (s + bi) * sc + sh;
    }
}

// ---------------- unit: depthwise 3x3 of Cm channel -> cmbuf ----------------
__device__ void cm_unit(float* sm, int u, const float* __restrict__ bcdt0,
                        const float* __restrict__ dw, float* __restrict__ cmbuf) {
    __syncthreads();
    float* pl = sm;         // 30x30
    float* wsh = sm + 900;  // 9
    int s = u & 63, b = u >> 6;
    const float* ip = bcdt0 + ((long)b * 192 + 64 + s) * NL;
    int t = threadIdx.x;
    for (int i = t; i < 900; i += 256) pl[i] = 0.f;
    if (t < 9) wsh[t] = dw[(64 + s) * 9 + t];
    __syncthreads();
    for (int i = t; i < NL; i += 256) {
        int y = i / NWW, x = i % NWW;
        pl[(y + 1) * 30 + x + 1] = ip[i];
    }
    __syncthreads();
    for (int i = t; i < NL; i += 256) {
        int y = i / NWW, x = i % NWW;
        float v = 0.f;
#pragma unroll
        for (int ky = 0; ky < 3; ky++)
#pragma unroll
            for (int kx = 0; kx < 3; kx++)
                v += wsh[ky * 3 + kx] * pl[(y + ky) * 30 + x + kx];
        cmbuf[((long)b * NC + s) * NL + i] = v;
    }
}

// ---------------- unit: branch 2 MRA (fused) ----------------
__device__ void mra_unit(float* sm, int u, const float* __restrict__ x,
                         const float* __restrict__ h1w, const float* __restrict__ v1w,
                         const float* __restrict__ h2w, const float* __restrict__ v2w,
                         const float* __restrict__ bnp, float* __restrict__ xa) {
    __syncthreads();
    float* xp = sm;            // 784
    float* mp = sm + 784;      // 784
    float* xs = mp + 784;      // 100
    float* ht = xs + 100;      // 190
    float* vt = ht + 190;      // 190
    float* c2 = vt + 190;      // 190
    float* c2v = c2 + 190;     // 190
    float* att_s = c2v + 190;  // 100
    int c = u & 63, b = u >> 6;
    const float* ip = x + ((long)b * ND + NC + c) * NL;
    int t = threadIdx.x;
    for (int i = t; i < NL; i += 256) xp[i] = ip[i];
    __syncthreads();
    for (int i = t; i < NL; i += 256) {
        int y = i / NWW, xx = i % NWW;
        float mx = -1e30f;
        for (int dy = -1; dy <= 1; dy++) {
            int yy = y + dy;
            if (yy < 0 || yy >= NHH) continue;
            for (int dx = -1; dx <= 1; dx++) {
                int xxx = xx + dx;
                if (xxx < 0 || xxx >= NWW) continue;
                mx = fmaxf(mx, xp[yy * NWW + xxx]);
            }
        }
        mp[i] = mx;
    }
    __syncthreads();
    if (t < 100) {
        int i = t / 10, j = t % 10;
        const float filt[4] = {1.f, 3.f, 3.f, 1.f};
        float s = 0.f;
        for (int fy = 0; fy < 4; fy++) {
            int oy = 3 * i + fy - 1;
            if (oy < 0) oy = -oy;
            if (oy >= NHH) oy = 2 * NHH - 2 - oy;
            for (int fx = 0; fx < 4; fx++) {
                int ox = 3 * j + fx - 1;
                if (ox < 0) ox = -ox;
                if (ox >= NWW) ox = 2 * NWW - 2 - ox;
                s += filt[fy] * filt[fx] * mp[oy * NWW + ox];
            }
        }
        xs[t] = s * (1.f / 64.f);
    }
    __syncthreads();
    if (t < 190) {
        {
            int row = t / 20, col = t % 20;
            ht[t] = (col < 10) ? xs[row * 10 + col] : 0.f;
        }
        {
            int a = t / 10, b2 = t % 10;
            int k = b2 * 19 + a, row = k / 20, col = k % 20;
            vt[t] = (col < 10) ? xs[col * 10 + row] : 0.f;
        }
    }
    __syncthreads();
    if (t < 190) {
        {
            int r = t / 19, j = t % 19;
            float s = 0.f;
            for (int ky = 0; ky < 11; ky++) {
                int yy = r + ky - 5;
                if (yy < 0 || yy >= 10) continue;
                for (int kx = 0; kx < 3; kx++) {
                    int xx = j + kx - 1;
                    if (xx < 0 || xx >= 19) continue;
                    s += h2w[c * 33 + ky * 3 + kx] * ht[yy * 19 + xx];
                }
            }
            c2[t] = s;
        }
        {
            int y = t / 10, x2 = t % 10;
            float s = 0.f;
            for (int ky = 0; ky < 3; ky++) {
                int yy = y + ky - 1;
                if (yy < 0 || yy >= 19) continue;
                for (int kx = 0; kx < 11; kx++) {
                    int xx = x2 + kx - 5;
                    if (xx < 0 || xx >= 10) continue;
                    s += v2w[c * 33 + ky * 11 + kx] * vt[yy * 10 + xx];
                }
            }
            c2v[t] = s;
        }
    }
    __syncthreads();
    if (t < 100) {
        int y = t / 10, xx = t % 10;
        float s = 0.f;
        for (int ky = 0; ky < 11; ky++) {
            int yy = y + ky - 5;
            if (yy < 0 || yy >= 10) continue;
            for (int kx = 0; kx < 3; kx++) {
                int xxx = xx + kx - 1;
                if (xxx < 0 || xxx >= 10) continue;
                s += h1w[c * 33 + ky * 3 + kx] * xs[yy * 10 + xxx];
            }
        }
        for (int ky = 0; ky < 3; ky++) {
            int yy = y + ky - 1;
            if (yy < 0 || yy >= 10) continue;
            for (int kx = 0; kx < 11; kx++) {
                int xxx = xx + kx - 5;
                if (xxx < 0 || xxx >= 10) continue;
                s += v1w[c * 33 + ky * 11 + kx] * xs[yy * 10 + xxx];
            }
        }
        s += c2[y * 20 + xx];
        int k4 = xx * 20 + y;
        s += c2v[(k4 % 19) * 10 + (k4 / 19)];
        float g = bnp[c], be = bnp[NC + c], mm = bnp[2 * NC + c], vv = bnp[3 * NC + c];
        float sc = g * rsqrtf(vv + 1e-5f);
        s = (s - mm) * sc + be;
        att_s[t] = 1.f / (1.f + __expf(-s));
    }
    __syncthreads();
    float* op = xa + (long)b * ND * NL + (long)(NC + c) * NL;
    for (int i = t; i < NL; i += 256) {
        int y = i / NWW, xx = i % NWW;
        op[i] = xp[i] * att_s[((y * 10) / NHH) * 10 + (xx * 10) / NWW];
    }
}

// ---------------- unit: SSD W (conv+softmax) + h-GEMM ----------------
__device__ void wh_unit(float* sm, int u, const float* __restrict__ x,
                        const float* __restrict__ bcdt0, const float* __restrict__ dw,
                        const float* __restrict__ A_param, float* __restrict__ h) {
    __syncthreads();
    float* Wsh = sm;  // 8 x 784
    int stile = u & 7, b = u >> 3;
    int warp = threadIdx.x / 32, lane = threadIdx.x % 32;
    {
        int s = stile * 8 + warp;
        float wd[9], wb[9];
#pragma unroll
        for (int k = 0; k < 9; k++) {
            wd[k] = dw[(128 + s) * 9 + k];
            wb[k] = dw[s * 9 + k];
        }
        const float* dtp = bcdt0 + ((long)b * 192 + 128 + s) * NL;
        const float* bmp = bcdt0 + ((long)b * 192 + s) * NL;
        float ap = A_param[s];
        float mx = -1e30f;
        for (int l = lane; l < NL; l += 32) {
            int y = l / NWW, xx = l % NWW;
            float v = 0.f;
#pragma unroll
            for (int ky = 0; ky < 3; ky++) {
                int yy = y + ky - 1;
                if (yy < 0 || yy >= NHH) continue;
#pragma unroll
                for (int kx = 0; kx < 3; kx++) {
                    int xxx = xx + kx - 1;
                    if (xxx < 0 || xxx >= NWW) continue;
                    v += wd[ky * 3 + kx] * dtp[yy * NWW + xxx];
                }
            }
            v += ap;
            Wsh[warp * NL + l] = v;
            mx = fmaxf(mx, v);
        }
#pragma unroll
        for (int o = 16; o > 0; o >>= 1)
            mx = fmaxf(mx, __shfl_xor_sync(0xffffffff, mx, o));
        float sum = 0.f;
        for (int l = lane; l < NL; l += 32) {
            float e = __expf(Wsh[warp * NL + l] - mx);
            Wsh[warp * NL + l] = e;
            sum += e;
        }
#pragma unroll
        for (int o = 16; o > 0; o >>= 1)
            sum += __shfl_xor_sync(0xffffffff, sum, o);
        float inv = 1.f / sum;
        for (int l = lane; l < NL; l += 32) {
            int y = l / NWW, xx = l % NWW;
            float v = 0.f;
#pragma unroll
            for (int ky = 0; ky < 3; ky++) {
                int yy = y + ky - 1;
                if (yy < 0 || yy >= NHH) continue;
#pragma unroll
                for (int kx = 0; kx < 3; kx++) {
                    int xxx = xx + kx - 1;
                    if (xxx < 0 || xxx >= NWW) continue;
                    v += wb[ky * 3 + kx] * bmp[yy * NWW + xxx];
                }
            }
            Wsh[warp * NL + l] *= inv * v;
        }
    }
    __syncthreads();
    for (int i = 0; i < 8; i++) {
        int c = i * 8 + warp;
        const float* xsrc = x + ((long)b * ND + 128 + c) * NL;
        float acc[8];
#pragma unroll
        for (int k = 0; k < 8; k++) acc[k] = 0.f;
        for (int l = lane; l < NL; l += 32) {
            float xv = xsrc[l];
#pragma unroll
            for (int k = 0; k < 8; k++) acc[k] += xv * Wsh[k * NL + l];
        }
#pragma unroll
        for (int k = 0; k < 8; k++) {
#pragma unroll
            for (int o = 16; o > 0; o >>= 1)
                acc[k] += __shfl_down_sync(0xffffffff, acc[k], o);
        }
        if (lane == 0) {
#pragma unroll
            for (int k = 0; k < 8; k++)
                h[((long)b * NC + c) * NS + stile * 8 + k] = acc[k];
        }
    }
}

// ---------------- unit: attention (256 rows) ----------------
__device__ void attn_unit(float* sm, int u, const float* __restrict__ qkv,
                          float* __restrict__ o) {
    __syncthreads();
    float* Ks = sm;
    float* Vs = sm + NL * 4;
    int chunk = u & 3, bh = u >> 2;
    int head = bh % NHEAD, b = bh / NHEAD;
    const float* kbase = qkv + ((long)b * 192 + 64 + head * 4) * NL;
    const float* vbase = qkv + ((long)b * 192 + 128 + head * 4) * NL;
    for (int i = threadIdx.x; i < NL * 4; i += 256) {
        int d = i / NL, l = i % NL;
        Ks[l * 4 + d] = kbase[i];
        Vs[l * 4 + d] = vbase[i];
    }
    __syncthreads();
    int row = chunk * 256 + threadIdx.x;
    if (row >= NL) return;
    const float* qb = qkv + ((long)b * 192 + head * 4) * NL;
    float q0 = qb[row] * 0.5f, q1 = qb[NL + row] * 0.5f;
    float q2 = qb[2 * NL + row] * 0.5f, q3 = qb[3 * NL + row] * 0.5f;
    float se = 0.f, a0 = 0.f, a1 = 0.f, a2 = 0.f, a3 = 0.f;
    const float4* K4 = reinterpret_cast<const float4*>(Ks);
    const float4* V4 = reinterpret_cast<const float4*>(Vs);
    for (int l = 0; l < NL; l++) {
        float4 kv = K4[l];
        float p = __expf(q0 * kv.x + q1 * kv.y + q2 * kv.z + q3 * kv.w);
        float4 vv = V4[l];
        se += p;
        a0 += p * vv.x; a1 += p * vv.y; a2 += p * vv.z; a3 += p * vv.w;
    }
    float inv = 1.f / se;
    float* ob = o + ((long)b * NC + head * 4) * NL;
    ob[row] = a0 * inv;
    ob[NL + row] = a1 * inv;
    ob[2 * NL + row] = a2 * inv;
    ob[3 * NL + row] = a3 * inv;
}

// ---------------- unit: SSD mix stage A (u = hz1(h)*(silu(hz2(h))+D)) ----------------
__device__ void mixA_unit(float* sm, int u, const float* __restrict__ h,
                          const float* __restrict__ hzw, const float* __restrict__ D,
                          float* __restrict__ ubuf) {
    __syncthreads();
    float* hs = sm;  // 64x64
    int b = u >> 3, o8 = (u & 7) * 8;
    int t = threadIdx.x;
    for (int i = t; i < NC * NS; i += 256) hs[i] = h[(long)b * NC * NS + i];
    __syncthreads();
    float Dv = D[0];
    int s = t & 63, ol = t >> 6;  // 4 o-lanes, 2 outputs each
#pragma unroll
    for (int k = 0; k < 2; k++) {
        int o = o8 + ol * 2 + k;
        const float* w1 = hzw + (long)o * NC;
        const float* w2 = hzw + (long)(NC + o) * NC;
        float a1 = 0.f, a2 = 0.f;
#pragma unroll 4
        for (int c = 0; c < NC; c++) {
            float hv = hs[c * NS + s];
            a1 += w1[c] * hv;
            a2 += w2[c] * hv;
        }
        float sil = a2 / (1.f + __expf(-a2));
        ubuf[((long)b * NC + o) * NS + s] = a1 * sil + a1 * Dv;
    }
}

// ---------------- unit: SSD out (h2 slice recomputed + @ cmbuf) ----------------
__device__ void sout_unit(float* sm, int u, const float* __restrict__ ubuf,
                          const float* __restrict__ ow, const float* __restrict__ cmbuf,
                          float* __restrict__ xa) {
    __syncthreads();
    float* us = sm;          // 64x64
    float* hst = sm + 4096;  // [s][16]
    int cg = u & 3, lt = (u >> 2) & 3, b = u >> 4;
    int t = threadIdx.x;
    for (int i = t; i < NC * NS; i += 256) us[i] = ubuf[(long)b * NC * NS + i];
    __syncthreads();
    for (int idx = t; idx < 1024; idx += 256) {
        int oi = idx & 15, s = idx >> 4;
        const float* wr = ow + (long)(cg * 16 + oi) * NC;
        float acc = 0.f;
#pragma unroll 4
        for (int c = 0; c < NC; c++) acc += wr[c] * us[c * NS + s];
        hst[s * 16 + oi] = acc;
    }
    __syncthreads();
    if (t >= 196) return;
    int l = lt * 196 + t;
    const float* Cm = cmbuf + (long)b * NC * NL + l;
    float acc[16];
#pragma unroll
    for (int i = 0; i < 16; i++) acc[i] = 0.f;
#pragma unroll 4
    for (int s = 0; s < NS; s++) {
        float cv = Cm[(long)s * NL];
        const float* hp = hst + s * 16;
#pragma unroll
        for (int i = 0; i < 16; i++) acc[i] += hp[i] * cv;
    }
#pragma unroll
    for (int i = 0; i < 16; i++)
        xa[(long)b * ND * NL + (long)(128 + cg * 16 + i) * NL + l] = acc[i];
}

// ---------------- megakernel ----------------
static constexpr int U_DW1 = 512, U_MRA = 512, U_PW13 = 156;  // 12 otiles x 13 pslots
static constexpr int P0_N = U_DW1 + U_MRA + 2 * U_PW13;       // 1336
static constexpr int U_STAR = 104, U_WH = 64, U_ATT = 512, U_CM = 512;
static constexpr int P1_N = U_STAR + U_WH + U_ATT + U_CM;     // 1192
static constexpr int U_PW4 = 52, U_MIXA = 64;
static constexpr int P2_N = 2 * U_PW4 + U_MIXA;               // 168
static constexpr int P3_N = 512 + 128;                        // 640
static constexpr int P4_N = 104;                              // mlp1: 8 x 13
static constexpr int P5_N = 208;                              // mlp2: 16 x 13

__global__ __launch_bounds__(256, 2) void mega_k(MegaParams p) {
    extern __shared__ float sm[];
    float* scr = g_scr;
    float* x1o = scr + O_X1O;
    float* t2 = scr + O_T2;
    float* tmp1 = scr + O_TMP1;
    float* bcdt0 = scr + O_BCDT0;
    float* cmbuf = scr + O_CM;
    float* hbuf = scr + O_H;
    float* ubuf = scr + O_U;
    float* qkv = scr + O_QKV;
    float* obuf = scr + O_O;
    float* xa = scr + O_XA;
    float* m1 = scr + O_M1;
    const long XBS = (long)ND * NL;
    const long C64 = (long)NC * NL;
    const long C128 = (long)NHID * NL;
    const long C192 = (long)192 * NL;

    // ---- phase 0 ----
    for (int u = blockIdx.x; u < P0_N; u += GRID) {
        if (u < U_DW1) {
            dw7_unit(sm, u, p.x, XBS, p.dw1_w, p.dw1_b, p.bn_dw1, x1o, C64);
        } else if (u < U_DW1 + U_MRA) {
            mra_unit(sm, u - U_DW1, p.x, p.h1w, p.v1w, p.h2w, p.v2w, p.bn_mra, xa);
        } else if (u < U_DW1 + U_MRA + U_PW13) {
            int v = u - U_DW1 - U_MRA;
            pw_unit<64>(sm, v % 12, v / 12, p.x + 128 * NL, XBS, p.bcdt_w, 192,
                        nullptr, nullptr, nullptr, 0, bcdt0, C192, M_NONE);
        } else {
            int v = u - U_DW1 - U_MRA - U_PW13;
            pw_unit<64>(sm, v % 12, v / 12, p.x + 192 * NL, XBS, p.qkv_w, 192,
                        nullptr, nullptr, nullptr, 0, qkv, C192, M_NONE);
        }
    }
    grid_barrier();

    // ---- phase 1 ----
    for (int u = blockIdx.x; u < P1_N; u += GRID) {
        if (u < U_STAR) {
            star_unit(sm, u % 8, u / 8, x1o, p.f1_w, p.f1_b, p.f2_w, p.f2_b, t2);
        } else if (u < U_STAR + U_WH) {
            wh_unit(sm, u - U_STAR, p.x, bcdt0, p.ssd_dw, p.A, hbuf);
        } else if (u < U_STAR + U_WH + U_ATT) {
            attn_unit(sm, u - U_STAR - U_WH, qkv, obuf);
        } else {
            cm_unit(sm, u - U_STAR - U_WH - U_ATT, bcdt0, p.ssd_dw, cmbuf);
        }
    }
    grid_barrier();

    // ---- phase 2 ----
    for (int u = blockIdx.x; u < P2_N; u += GRID) {
        if (u < U_PW4) {
            pw_unit<128>(sm, u % 4, u / 4, t2, C128, p.g_w, NC, p.g_b, p.bn_g,
                         nullptr, 0, tmp1, C64, M_BN);
        } else if (u < 2 * U_PW4) {
            int v = u - U_PW4;
            pw_unit<64>(sm, v % 4, v / 4, obuf, C64, p.proj_w, NC, nullptr, p.bn_n4,
                        p.x + 192 * NL, XBS, xa + 192 * NL, XBS, M_ADD_BN);
        } else {
            mixA_unit(sm, u - 2 * U_PW4, hbuf, p.hz_w, p.D, ubuf);
        }
    }
    grid_barrier();

    // ---- phase 3 ----
    for (int u = blockIdx.x; u < P3_N; u += GRID) {
        if (u < 512) {
            dw7_unit(sm, u, tmp1, C64, p.dw2_w, p.dw2_b, nullptr, xa, XBS);
        } else {
            sout_unit(sm, u - 512, ubuf, p.ow, cmbuf, xa);
        }
    }
    grid_barrier();

    // ---- phase 4: mlp1 ----
    for (int u = blockIdx.x; u < P4_N; u += GRID)
        pw_unit<256>(sm, u % 8, u / 8, xa, XBS, p.mlp1_w, NHID, nullptr, p.bn_mlp,
                     nullptr, 0, m1, C128, M_BN_RELU);
    grid_barrier();

    // ---- phase 5: mlp2 + residual ----
    for (int u = blockIdx.x; u < P5_N; u += GRID)
        pw_unit<128>(sm, u % 16, u / 16, m1, C128, p.mlp2_w, ND, nullptr, p.bn_n1,
                     p.x, XBS, p.out, XBS, M_BN_ADD);
}

// ---------------- launch ----------------
static constexpr int SMEM_MEGA = 8 * NL * 4;  // 25,088 B (attn / Wsh are the max)

extern "C" void kernel_launch(void* const* d_in, const int* in_sizes, int n_in,
                              void* d_out, int out_size) {
    MegaParams p;
    p.x       = (const float*)d_in[0];
    p.dw1_w   = (const float*)d_in[1];
    p.dw1_b   = (const float*)d_in[2];
    p.bn_dw1  = (const float*)d_in[3];
    p.f1_w    = (const float*)d_in[4];
    p.f1_b    = (const float*)d_in[5];
    p.f2_w    = (const float*)d_in[6];
    p.f2_b    = (const float*)d_in[7];
    p.g_w     = (const float*)d_in[8];
    p.g_b     = (const float*)d_in[9];
    p.bn_g    = (const float*)d_in[10];
    p.dw2_w   = (const float*)d_in[11];
    p.dw2_b   = (const float*)d_in[12];
    p.h1w     = (const float*)d_in[13];
    p.v1w     = (const float*)d_in[14];
    p.h2w     = (const float*)d_in[15];
    p.v2w     = (const float*)d_in[16];
    p.bn_mra  = (const float*)d_in[17];
    p.bcdt_w  = (const float*)d_in[18];
    p.ssd_dw  = (const float*)d_in[19];
    p.hz_w    = (const float*)d_in[20];
    p.ow      = (const float*)d_in[21];
    p.A       = (const float*)d_in[22];
    p.D       = (const float*)d_in[23];
    p.qkv_w   = (const float*)d_in[24];
    p.proj_w  = (const float*)d_in[25];
    p.bn_n4   = (const float*)d_in[26];
    p.mlp1_w  = (const float*)d_in[27];
    p.bn_mlp  = (const float*)d_in[28];
    p.mlp2_w  = (const float*)d_in[29];
    p.bn_n1   = (const float*)d_in[30];
    p.out     = (float*)d_out;

    static bool configured = false;
    if (!configured) {
        cudaFuncSetAttribute(mega_k, cudaFuncAttributeMaxDynamicSharedMemorySize,
                             SMEM_MEGA);
        configured = true;
    }
    mega_k<<<GRID, 256, SMEM_MEGA>>>(p);
}